// round 11
// baseline (speedup 1.0000x reference)
#include <cuda_runtime.h>

// SpikingAttentionJAX — ONE kernel, ZERO grid sync, atomicMax global top-5.
// LIF scan collapses to per-token occurrence counts (per-entry updates
// commute; entry t's final state depends only on count n_t and v0[t]).
//
// 125 blocks x 1024 threads; block b owns vocab slice [1024b, 1024b+1024).
// Each block histograms the whole 8192-token stream (8 tokens/thread, two
// independent int4 loads, L2-broadcast) into shared memory; v0 prefetched
// before the scan to hide its DRAM latency. Then LIF replay, gain store
// (0.6 spiked / 1.0), REDUX warp top-5, warp0 block merge.
//
// Global top-5 via concurrent atomicMax insertion: lanes 0-4 of warp 0 each
// insert one packed key (ordered_float(v)<<32 | ~idx — monotone, unique,
// JAX lower-index tie-break) into g_top[5] with a displace-and-carry chain:
//   for j: old = atomicMax(&g_top[j], k); k = min(k, old)
// A rank-r key is displaced at most r times, so the true top-5 always ends
// in the slots. Finalizer (last block via done-counter, no spinning) just
// reads the 5 slots, writes out[idx] = 1.5, and resets the slots to zero
// (restores the invariant for the next graph replay).

static constexpr float DECAY     = 0.7f;
static constexpr float THETA     = 1.0f;
static constexpr float GAIN_UP   = 1.5f;
static constexpr float GAIN_DOWN = 0.6f;
static constexpr int   KW   = 5;
static constexpr int   NT   = 1024;
static constexpr int   NW   = NT / 32;       // 32 warps

__device__ unsigned long long g_top[KW];     // zero-init; reset each replay
__device__ unsigned g_done = 0;              // monotonic across graph replays

__device__ __forceinline__ unsigned ordered_bits(float f) {
    unsigned u = __float_as_uint(f);
    return (u & 0x80000000u) ? ~u : (u | 0x80000000u);   // >0 for finite f
}

__global__ __launch_bounds__(NT)
void k_main(const int* __restrict__ tok, const float* __restrict__ v0,
            float* __restrict__ out, int seq, int vocab, int nblocks) {
    const int tid  = threadIdx.x;
    const int lane = tid & 31;
    const int wid  = tid >> 5;
    const int base = blockIdx.x * NT;            // this block's vocab slice
    const int i    = base + tid;                 // this thread's vocab entry
    const bool live = (i < vocab);

    __shared__ int      sh_cnt[NT];
    __shared__ unsigned s_val[NW * KW];          // 160 block candidates
    __shared__ unsigned s_idx[NW * KW];
    __shared__ unsigned s_last;

    // ---- prefetch v0 early: independent of histogram, hides DRAM latency ----
    float vpre = live ? __ldg(&v0[i]) : 0.0f;

    sh_cnt[tid] = 0;
    __syncthreads();

    // ---- histogram whole token stream for this slice (2 indep int4/thread) ----
    const int4* tok4 = reinterpret_cast<const int4*>(tok);
    const int   n4   = seq >> 2;                 // 2048
    int4 ta, tb;
    const bool hasA = (tid < n4), hasB = (tid + NT < n4);
    if (hasA) ta = __ldg(&tok4[tid]);
    if (hasB) tb = __ldg(&tok4[tid + NT]);
    if (hasA) {
        int t;
        t = ta.x; t = t < 0 ? 0 : (t >= vocab ? vocab - 1 : t);
        if ((unsigned)(t - base) < (unsigned)NT) atomicAdd(&sh_cnt[t - base], 1);
        t = ta.y; t = t < 0 ? 0 : (t >= vocab ? vocab - 1 : t);
        if ((unsigned)(t - base) < (unsigned)NT) atomicAdd(&sh_cnt[t - base], 1);
        t = ta.z; t = t < 0 ? 0 : (t >= vocab ? vocab - 1 : t);
        if ((unsigned)(t - base) < (unsigned)NT) atomicAdd(&sh_cnt[t - base], 1);
        t = ta.w; t = t < 0 ? 0 : (t >= vocab ? vocab - 1 : t);
        if ((unsigned)(t - base) < (unsigned)NT) atomicAdd(&sh_cnt[t - base], 1);
    }
    if (hasB) {
        int t;
        t = tb.x; t = t < 0 ? 0 : (t >= vocab ? vocab - 1 : t);
        if ((unsigned)(t - base) < (unsigned)NT) atomicAdd(&sh_cnt[t - base], 1);
        t = tb.y; t = t < 0 ? 0 : (t >= vocab ? vocab - 1 : t);
        if ((unsigned)(t - base) < (unsigned)NT) atomicAdd(&sh_cnt[t - base], 1);
        t = tb.z; t = t < 0 ? 0 : (t >= vocab ? vocab - 1 : t);
        if ((unsigned)(t - base) < (unsigned)NT) atomicAdd(&sh_cnt[t - base], 1);
        t = tb.w; t = t < 0 ? 0 : (t >= vocab ? vocab - 1 : t);
        if ((unsigned)(t - base) < (unsigned)NT) atomicAdd(&sh_cnt[t - base], 1);
    }
    // generic tails (inactive for seq=8192, NT=1024)
    for (int c = (n4 > 2 * NT ? 2 * NT : n4) + tid; c < n4; c += NT) {
        int4 t4 = __ldg(&tok4[c]);
        int t;
        t = t4.x; t = t < 0 ? 0 : (t >= vocab ? vocab - 1 : t);
        if ((unsigned)(t - base) < (unsigned)NT) atomicAdd(&sh_cnt[t - base], 1);
        t = t4.y; t = t < 0 ? 0 : (t >= vocab ? vocab - 1 : t);
        if ((unsigned)(t - base) < (unsigned)NT) atomicAdd(&sh_cnt[t - base], 1);
        t = t4.z; t = t < 0 ? 0 : (t >= vocab ? vocab - 1 : t);
        if ((unsigned)(t - base) < (unsigned)NT) atomicAdd(&sh_cnt[t - base], 1);
        t = t4.w; t = t < 0 ? 0 : (t >= vocab ? vocab - 1 : t);
        if ((unsigned)(t - base) < (unsigned)NT) atomicAdd(&sh_cnt[t - base], 1);
    }
    for (int c = (n4 << 2) + tid; c < seq; c += NT) {
        int t = __ldg(&tok[c]);
        t = t < 0 ? 0 : (t >= vocab ? vocab - 1 : t);
        if ((unsigned)(t - base) < (unsigned)NT) atomicAdd(&sh_cnt[t - base], 1);
    }
    __syncthreads();

    // ---- LIF replay + gains ----
    unsigned uval = 0u;                          // 0 = invalid/popped sentinel
    unsigned idx  = (unsigned)i;
    if (live) {
        int   cnt = sh_cnt[tid];
        float v   = vpre;
        int s = 0;
        for (int it = 0; it < cnt; it++) {
            float vn = DECAY * v + 1.0f;
            if (vn >= THETA) { v = vn - THETA; s++; }
            else             { v = vn; }
        }
        out[i] = (s > 0) ? GAIN_DOWN : 1.0f;
        uval = ordered_bits(v);
    }

    // ---- warp top-5: REDUX.UMAX(value) + REDUX.UMIN(index) per round ----
    #pragma unroll
    for (int r = 0; r < KW; r++) {
        unsigned m    = __reduce_max_sync(0xffffffffu, uval);
        unsigned cand = (uval == m) ? idx : 0xffffffffu;
        unsigned wi   = __reduce_min_sync(0xffffffffu, cand);
        if (lane == 0) { s_val[wid * KW + r] = m; s_idx[wid * KW + r] = wi; }
        if (uval == m && idx == wi) uval = 0u;
    }
    __syncthreads();

    // ---- warp 0: merge 160 (val,idx) -> block top-5 -> atomicMax insert ----
    if (wid == 0) {
        unsigned av[KW], ai[KW];                 // 5 slots per lane, static idx
        #pragma unroll
        for (int s = 0; s < KW; s++) {
            av[s] = s_val[s * 32 + lane];
            ai[s] = s_idx[s * 32 + lane];
        }
        unsigned long long mykey = 0ull;         // lane r keeps round-r winner
        #pragma unroll
        for (int r = 0; r < KW; r++) {
            unsigned bv = av[0], bi = ai[0];
            #pragma unroll
            for (int s = 1; s < KW; s++) {
                bool better = (av[s] > bv) || (av[s] == bv && ai[s] < bi);
                if (better) { bv = av[s]; bi = ai[s]; }
            }
            unsigned m    = __reduce_max_sync(0xffffffffu, bv);
            unsigned cand = (bv == m) ? bi : 0xffffffffu;
            unsigned wi   = __reduce_min_sync(0xffffffffu, cand);
            if (lane == r)
                mykey = ((unsigned long long)m << 32) |
                        (unsigned long long)(0xffffffffu - wi);
            #pragma unroll
            for (int s = 0; s < KW; s++)
                if (av[s] == m && ai[s] == wi) { av[s] = 0u; ai[s] = 0xffffffffu; }
        }
        // concurrent top-5 insertion: displace-and-carry atomicMax chain.
        if (lane < KW) {
            unsigned long long c = mykey;        // nonzero: real key
            #pragma unroll
            for (int j = 0; j < KW; j++) {
                unsigned long long old = atomicMax(&g_top[j], c);
                c = (old < c) ? old : c;         // carry the displaced value
            }
        }
    }

    // ---- done-counter: last-arriving block finalizes (no spinning) ----
    if (tid == 0) {
        __threadfence();                         // publish out[] stores
        unsigned old = atomicAdd(&g_done, 1);
        s_last = (((old + 1) % (unsigned)nblocks) == 0u) ? 1u : 0u;
    }
    __syncthreads();
    if (!s_last) return;

    // finalize: slots already hold the global top-5 (atomics committed at L2
    // before each block's done-increment, whose return ordered them).
    if (tid < KW) {
        unsigned long long b = atomicAdd(&g_top[tid], 0ull);  // coherent read
        unsigned oidx = 0xffffffffu - (unsigned)(b & 0xffffffffull);
        out[oidx] = GAIN_UP;                     // all 5 slots hold real keys
        g_top[tid] = 0ull;                       // reset for next graph replay
    }
}

// ---------------------------------------------------------------- launch
extern "C" void kernel_launch(void* const* d_in, const int* in_sizes, int n_in,
                              void* d_out, int out_size) {
    const int*   tok = (const int*)d_in[0];
    const float* v0  = (const float*)d_in[1];
    const int seq   = in_sizes[0];
    const int vocab = in_sizes[1];
    float* out = (float*)d_out;

    int gblocks = (vocab + NT - 1) / NT;         // 125 for vocab=128000
    k_main<<<gblocks, NT>>>(tok, v0, out, seq, vocab, gblocks);
}